// round 15
// baseline (speedup 1.0000x reference)
#include <cuda_runtime.h>
#include <cuda_fp16.h>
#include <math.h>
#include <stdint.h>

#define N_TOKENS 65536
#define EMB_DIM  128
#define NUM_EMB  1024

// Output tuple flattened scalar-wise in reference-return order:
// (e_latent_loss, quantized_st[N,D], perplexity, encodings[N,K])
#define OUT_LOSS 0
#define OUT_Q    1
#define OUT_PERP (1 + N_TOKENS * EMB_DIM)        // 8388609
#define OUT_ENC  (2 + N_TOKENS * EMB_DIM)        // 8388610 (even -> 8B-aligned)

#define BM   128
#define NBLK (N_TOKENS / BM)     // 512
#define NTHR 512
#define CAP  32                  // candidate list capacity per token

#define APAD 68                  // A tile: half2 stride per k-row
#define BPAD 132                 // B tile: half2 stride per k-row (dup'd codes)

// dynamic smem layout (bytes)
#define SM_A    0                // 34816 : A fp16 [k][tokenpair] half2
#define SM_B0   34816            // 16896 : B buffer 0
#define SM_B1   51712            // 16896 : B buffer 1
#define SM_SXP  68608            // 4096  : double sx partials[512]
#define SM_SXF  72704            // 512   : float sx[128]
#define SM_CNT  73216            // 512   : int scnt[128]
#define SM_LIST 73728            // 8192  : uint16 slist[128][CAP]
#define DSMEM   81920
// epilogue reuse inside SM_A (after screening):
#define SM2_SBK  0               // 512  : int bk[128]
#define SM2_LRED 512             // 4096 : double lred[512]
#define SM2_LACC 4608            // 4096 : double lacc[512]

__device__ __align__(16) __half g_ehalfT[EMB_DIM * NUM_EMB]; // [k][code], e*1024
__device__ float  g_be[NUM_EMB];     // fl32 of exact ||e_k||^2
__device__ int    g_hist[NUM_EMB];   // code counts
__device__ double g_lpart[NBLK];     // per-block loss partials
__device__ unsigned int g_done;      // last-block-done counter

__device__ __forceinline__ double wsumd(double v) {
#pragma unroll
    for (int o = 16; o > 0; o >>= 1) v += __shfl_down_sync(~0u, v, o);
    return v;   // valid on lane 0
}

// exact sequential-k fp32 dot (reference accumulation order), float4 loads
__device__ __forceinline__ float exact_dot(const float* __restrict__ xr,
                                           const float* __restrict__ er) {
    const float4* x4 = (const float4*)xr;
    const float4* e4 = (const float4*)er;
    float dot = 0.f;
#pragma unroll 4
    for (int q = 0; q < EMB_DIM / 4; q++) {
        float4 xv = x4[q], ev = e4[q];
        dot = __fmaf_rn(xv.x, ev.x, dot);
        dot = __fmaf_rn(xv.y, ev.y, dot);
        dot = __fmaf_rn(xv.z, ev.z, dot);
        dot = __fmaf_rn(xv.w, ev.w, dot);
    }
    return dot;
}

// ---------------------------------------------------------------------------
// prep: exact double code norms; transposed fp16 codebook scaled by 1024
// (keeps values out of fp16 subnormals); zero hist/done. Warp per code.
// ---------------------------------------------------------------------------
__global__ void vq_prep_kernel(const float* __restrict__ emb) {
    const int gtid = blockIdx.x * 256 + threadIdx.x;   // 32768 threads
    const int code = gtid >> 5, lane = gtid & 31;
    float4 v = ((const float4*)emb)[code * 32 + lane];
    double s;
    { double a = v.x, b = v.y, c = v.z, d = v.w; s = a*a + b*b + c*c + d*d; }
    float arr[4] = {v.x, v.y, v.z, v.w};
#pragma unroll
    for (int i = 0; i < 4; i++)
        g_ehalfT[(size_t)(lane * 4 + i) * NUM_EMB + code] =
            __float2half_rn(arr[i] * 1024.0f);
    s = wsumd(s);
    if (lane == 0) { g_be[code] = (float)s; g_hist[code] = 0; }
    if (gtid == 0) g_done = 0;
}

// ---------------------------------------------------------------------------
// main: fp16 HFMA2 screening GEMM, 512 threads (8 warps/SMSP at occ 2) with
// double-buffered B staging, half-warp shfl fold, exact fp32 rescore (R3
// bit-exact chain) + fused outputs.
// ---------------------------------------------------------------------------
__global__ __launch_bounds__(NTHR, 2)
void vq_main_kernel(const float* __restrict__ x,
                    const float* __restrict__ emb,
                    float* __restrict__ out)
{
    extern __shared__ __align__(16) char dsm[];
    double*    sxp   = (double*)(dsm + SM_SXP);
    float*     sxf   = (float*)(dsm + SM_SXF);
    int*       scnt  = (int*)(dsm + SM_CNT);
    uint16_t*  slist = (uint16_t*)(dsm + SM_LIST);

    const int tid = threadIdx.x;          // 512
    const int tx  = tid & 15;             // codes tx + 16j (strided, cf-free)
    const int ty  = tid >> 4;             // 0..31: token pairs ty*2, ty*2+1
    const int m0  = blockIdx.x * BM;

    // ---- zero this block's one-hot rows (big DRAM op, overlaps GEMM) ----
    {
        float2* enc2 = (float2*)(out + OUT_ENC);
        size_t base = (size_t)m0 * (NUM_EMB / 2);
        for (int i = tid; i < BM * NUM_EMB / 2; i += NTHR)
            enc2[base + i] = make_float2(0.f, 0.f);
    }

    // ---- A tile: x -> fp16 [k][tokenpair]; fused sx partials (double) ----
    {
        const int t = tid >> 2, q = tid & 3;     // row t, k-quarter q
        const float4* xr = (const float4*)(x + (size_t)(m0 + t) * EMB_DIM)
                           + q * 8;
        const int pair = t >> 1, ln = t & 1;
        double sp = 0.0;
#pragma unroll
        for (int c = 0; c < 8; c++) {
            float4 v = xr[c];
            const int k = q * 32 + c * 4;
            float arr[4] = {v.x, v.y, v.z, v.w};
#pragma unroll
            for (int i = 0; i < 4; i++)
                *(__half*)(dsm + SM_A + (size_t)((k + i) * APAD + pair) * 4
                           + ln * 2) = __float2half_rn(arr[i]);
            double a = v.x, b = v.y, cc = v.z, d = v.w;
            sp += a * a; sp += b * b; sp += cc * cc; sp += d * d;
        }
        sxp[tid] = sp;   // partial: token t, quarter q (tid = t*4+q)
    }
    if (tid < 128) scnt[tid] = 0;
    __syncthreads();
    if (tid < 128)
        sxf[tid] = (float)(((sxp[tid*4] + sxp[tid*4+1])
                          + sxp[tid*4+2]) + sxp[tid*4+3]);  // fixed order
    __syncthreads();

    // per-token running min / margin in registers (tokens 4ty .. 4ty+3)
    float rmin[2][2], delta[2][2];
#pragma unroll
    for (int p = 0; p < 2; p++)
#pragma unroll
        for (int q = 0; q < 2; q++) {
            rmin[p][q]  = INFINITY;
            const float sx = sxf[ty * 4 + 2 * p + q];
            delta[p][q] = 2e-3f * fmaxf(1.0f, sqrtf(sx * 0.0078125f));
        }

    // ---- screening: 32 stages (ct = s>>2, ks = s&3), double-buffered B ----
    const int lr_c2 = tid & 63;           // staging: code pair
    const int lr_k0 = tid >> 6;           // staging: k base (0..7), step 8
    unsigned u[4];
    // prologue: prefetch stage 0
    {
        const __half* Esrc = g_ehalfT;    // ks=0, ct=0
#pragma unroll
        for (int r = 0; r < 4; r++)
            u[r] = *(const unsigned*)(Esrc
                + (size_t)(r * 8 + lr_k0) * NUM_EMB + lr_c2 * 2);
    }

    half2 acc[2][8];
    for (int s = 0; s < 32; s++) {
        char* buf = dsm + (s & 1 ? SM_B1 : SM_B0);
        // store prefetched chunk (dup'd) into this stage's buffer
#pragma unroll
        for (int r = 0; r < 4; r++) {
            const int k = r * 8 + lr_k0;
            half2 dlo = __half2half2(
                __ushort_as_half((unsigned short)(u[r] & 0xffffu)));
            half2 dhi = __half2half2(
                __ushort_as_half((unsigned short)(u[r] >> 16)));
            uint2 w; w.x = *(unsigned*)&dlo; w.y = *(unsigned*)&dhi;
            *(uint2*)(buf + (size_t)(k * BPAD + lr_c2 * 2) * 4) = w;
        }
        __syncthreads();

        // prefetch next stage (hidden behind compute)
        if (s < 31) {
            const int sn = s + 1;
            const __half* Esrc = g_ehalfT
                + (size_t)((sn & 3) * 32) * NUM_EMB + (sn >> 2) * 128;
#pragma unroll
            for (int r = 0; r < 4; r++)
                u[r] = *(const unsigned*)(Esrc
                    + (size_t)(r * 8 + lr_k0) * NUM_EMB + lr_c2 * 2);
        }

        if ((s & 3) == 0) {
#pragma unroll
            for (int p = 0; p < 2; p++)
#pragma unroll
                for (int j = 0; j < 8; j++)
                    acc[p][j] = __half2half2(
                        __ushort_as_half((unsigned short)0));
        }

        // HFMA2 inner loop over this 32-k chunk
#pragma unroll 4
        for (int k = 0; k < 32; k++) {
            const int kg = (s & 3) * 32 + k;
            uint2 av = *(const uint2*)(dsm + SM_A
                + (size_t)(kg * APAD + ty * 2) * 4);
            half2 a0 = *(half2*)&av.x, a1 = *(half2*)&av.y;
            const half2* br = (const half2*)buf + k * BPAD;
#pragma unroll
            for (int j = 0; j < 8; j++) {
                half2 b = br[tx + 16 * j];        // conflict-free LDS.32
                acc[0][j] = __hfma2(a0, b, acc[0][j]);
                acc[1][j] = __hfma2(a1, b, acc[1][j]);
            }
        }

        // ---- end of ct: half-warp fold (no block sync) ----
        if ((s & 3) == 3) {
            const int ct = s >> 2;
            float tmin[2][2];
#pragma unroll
            for (int p = 0; p < 2; p++) { tmin[p][0] = INFINITY; tmin[p][1] = INFINITY; }
#pragma unroll
            for (int j = 0; j < 8; j++) {
                const int kk = ct * 128 + tx + 16 * j;
                const float be = __ldg(&g_be[kk]);
#pragma unroll
                for (int p = 0; p < 2; p++) {
                    float2 df = __half22float2(acc[p][j]);
                    // s = be - 2*dot = be - (2/1024)*dot'  (exact pow2 scale)
                    tmin[p][0] = fminf(tmin[p][0],
                                       __fmaf_rn(-0.001953125f, df.x, be));
                    tmin[p][1] = fminf(tmin[p][1],
                                       __fmaf_rn(-0.001953125f, df.y, be));
                }
            }
            // butterfly min across the 16 owner lanes (order-independent)
#pragma unroll
            for (int m = 1; m <= 8; m <<= 1)
#pragma unroll
                for (int p = 0; p < 2; p++) {
                    tmin[p][0] = fminf(tmin[p][0],
                        __shfl_xor_sync(~0u, tmin[p][0], m));
                    tmin[p][1] = fminf(tmin[p][1],
                        __shfl_xor_sync(~0u, tmin[p][1], m));
                }
            float thr[2][2];
#pragma unroll
            for (int p = 0; p < 2; p++)
#pragma unroll
                for (int q = 0; q < 2; q++) {
                    rmin[p][q] = fminf(rmin[p][q], tmin[p][q]);
                    thr[p][q]  = rmin[p][q] + delta[p][q];
                }
#pragma unroll
            for (int j = 0; j < 8; j++) {
                const int kk = ct * 128 + tx + 16 * j;
                const float be = __ldg(&g_be[kk]);
#pragma unroll
                for (int p = 0; p < 2; p++) {
                    float2 df = __half22float2(acc[p][j]);
                    const int t0 = ty * 4 + 2 * p;
                    float s0 = __fmaf_rn(-0.001953125f, df.x, be);
                    float s1 = __fmaf_rn(-0.001953125f, df.y, be);
                    if (s0 <= thr[p][0]) {
                        int i = atomicAdd(scnt + t0, 1);
                        if (i < CAP) slist[t0 * CAP + i] = (uint16_t)kk;
                    }
                    if (s1 <= thr[p][1]) {
                        int i = atomicAdd(scnt + t0 + 1, 1);
                        if (i < CAP) slist[(t0 + 1) * CAP + i] = (uint16_t)kk;
                    }
                }
            }
        }
    }
    __syncthreads();   // lists complete; SM_A free for epilogue reuse

    // ---- phase 2: exact rescore (R3 bit-exact arithmetic) ----
    int*    s_bk = (int*)(dsm + SM2_SBK);
    double* lred = (double*)(dsm + SM2_LRED);
    double* lacc = (double*)(dsm + SM2_LACC);
    if (tid < 128) {
        const int row = m0 + tid;
        const float sxe = sxf[tid];
        const float* xr = x + (size_t)row * EMB_DIM;
        float bv = INFINITY;
        int   bk = 0;
        const int nc = scnt[tid];
        if (nc <= 0 || nc > CAP) {
            // safety fallback: full exact scan (nc>=1 is structural)
            for (int k = 0; k < NUM_EMB; k++) {
                float dot = exact_dot(xr, emb + (size_t)k * EMB_DIM);
                float d = __fsub_rn(__fadd_rn(sxe, g_be[k]),
                                    __fmul_rn(2.0f, dot));
                if (d < bv || (d == bv && k < bk)) { bv = d; bk = k; }
            }
        } else {
            bk = NUM_EMB - 1;
            // min over candidate set: order-independent -> deterministic
            for (int i = 0; i < nc; i++) {
                const int k = slist[tid * CAP + i];
                float dot = exact_dot(xr, emb + (size_t)k * EMB_DIM);
                float d = __fsub_rn(__fadd_rn(sxe, g_be[k]),
                                    __fmul_rn(2.0f, dot));
                if (d < bv || (d == bv && k < bk)) { bv = d; bk = k; }
            }
        }
        s_bk[tid] = bk;
        out[(size_t)OUT_ENC + (size_t)row * NUM_EMB + bk] = 1.0f;
        atomicAdd(&g_hist[bk], 1);   // integer atomic: deterministic
    }
    __syncthreads();

    // ---- cooperative coalesced quantized_st + loss (32-bit stores) ----
    double lsum = 0.0;
    float* oq = out + OUT_Q + (size_t)m0 * EMB_DIM;
    const float* xq = x + (size_t)m0 * EMB_DIM;
    for (int e = tid; e < BM * EMB_DIM; e += NTHR) {
        const int row = e >> 7;
        const int col = e & 127;
        const float xv = xq[e];
        const float qv = emb[(size_t)s_bk[row] * EMB_DIM + col];
        const float d  = __fsub_rn(qv, xv);
        oq[e] = __fadd_rn(xv, d);        // fl(x + fl(q-x)), exact STE math
        lsum += (double)d * (double)d;
    }
    lred[tid] = lsum;
    __syncthreads();
    for (int s = NTHR / 2; s > 0; s >>= 1) {
        if (tid < s) lred[tid] += lred[tid + s];
        __syncthreads();
    }
    if (tid == 0) g_lpart[blockIdx.x] = lred[0];

    // ---- last block computes the scalars (fused finalize) ----
    __shared__ bool is_last;
    __threadfence();
    if (tid == 0) {
        unsigned v = atomicAdd(&g_done, 1u);
        is_last = (v == NBLK - 1);
    }
    __syncthreads();
    if (!is_last) return;

    double ent = 0.0;
#pragma unroll
    for (int b = 0; b < 2; b++) {
        double pr = (double)g_hist[tid * 2 + b] / (double)N_TOKENS;
        ent += pr * log(pr + 1e-10);
    }
    double ls = g_lpart[tid];            // NBLK == NTHR == 512
    lred[tid] = ent;
    lacc[tid] = ls;
    __syncthreads();
    for (int s = NTHR / 2; s > 0; s >>= 1) {
        if (tid < s) { lred[tid] += lred[tid + s]; lacc[tid] += lacc[tid + s]; }
        __syncthreads();
    }
    if (tid == 0) {
        out[OUT_PERP] = (float)exp(-lred[0]);
        out[OUT_LOSS] = (float)(lacc[0] / ((double)N_TOKENS * (double)EMB_DIM));
    }
}

// ---------------------------------------------------------------------------
extern "C" void kernel_launch(void* const* d_in, const int* in_sizes, int n_in,
                              void* d_out, int out_size) {
    const float* x   = (const float*)d_in[0];   // inputs [65536,128]
    const float* emb = (const float*)d_in[1];   // emb_w  [1024,128]
    float* out = (float*)d_out;

    cudaFuncSetAttribute(vq_main_kernel,
                         cudaFuncAttributeMaxDynamicSharedMemorySize, DSMEM);
    vq_prep_kernel<<<NUM_EMB * 32 / 256, 256>>>(emb);
    vq_main_kernel<<<NBLK, NTHR, DSMEM>>>(x, emb, out);
}

// round 16
// speedup vs baseline: 1.0211x; 1.0211x over previous
#include <cuda_runtime.h>
#include <cuda_fp16.h>
#include <math.h>
#include <stdint.h>

#define N_TOKENS 65536
#define EMB_DIM  128
#define NUM_EMB  1024

// Output tuple flattened scalar-wise in reference-return order:
// (e_latent_loss, quantized_st[N,D], perplexity, encodings[N,K])
#define OUT_LOSS 0
#define OUT_Q    1
#define OUT_PERP (1 + N_TOKENS * EMB_DIM)        // 8388609
#define OUT_ENC  (2 + N_TOKENS * EMB_DIM)        // 8388610 (even -> 8B-aligned)

#define BM   128
#define NBLK (N_TOKENS / BM)     // 512
#define NTHR 128
#define CAP  32                  // candidate list capacity per token

#define APAD 68                  // A tile: half2 stride per k-row
#define BPAD 132                 // B tile: half2 stride per k-row (dup'd codes)

// dynamic smem layout (bytes)
#define SM_A    0                // 34816 : A fp16 [k][tokenpair] half2
#define SM_B0   34816            // 16896 : B buffer 0
#define SM_B1   51712            // 16896 : B buffer 1
#define SM_SXF  68608            // 512   : float sx[128]
#define SM_CNT  69120            // 512   : int scnt[128]
#define SM_LIST 69632            // 8192  : uint16 slist[128][CAP]
#define DSMEM   77824
// epilogue reuse inside SM_A (after screening):
#define SM2_SBK  0               // 512  : int bk[128]
#define SM2_LRED 512             // 1024 : double lred[128]
#define SM2_LACC 1536            // 1024 : double lacc[128]

__device__ __align__(16) __half g_ehalfT[EMB_DIM * NUM_EMB]; // [k][code], e*1024
__device__ float  g_be[NUM_EMB];     // fl32 of exact ||e_k||^2
__device__ int    g_hist[NUM_EMB];   // code counts
__device__ double g_lpart[NBLK];     // per-block loss partials
__device__ unsigned int g_done;      // last-block-done counter

__device__ __forceinline__ double wsumd(double v) {
#pragma unroll
    for (int o = 16; o > 0; o >>= 1) v += __shfl_down_sync(~0u, v, o);
    return v;   // valid on lane 0
}

// exact sequential-k fp32 dot (reference accumulation order), float4 loads
__device__ __forceinline__ float exact_dot(const float* __restrict__ xr,
                                           const float* __restrict__ er) {
    const float4* x4 = (const float4*)xr;
    const float4* e4 = (const float4*)er;
    float dot = 0.f;
#pragma unroll 4
    for (int q = 0; q < EMB_DIM / 4; q++) {
        float4 xv = x4[q], ev = e4[q];
        dot = __fmaf_rn(xv.x, ev.x, dot);
        dot = __fmaf_rn(xv.y, ev.y, dot);
        dot = __fmaf_rn(xv.z, ev.z, dot);
        dot = __fmaf_rn(xv.w, ev.w, dot);
    }
    return dot;
}

// ---------------------------------------------------------------------------
// prep: exact double code norms; transposed fp16 codebook scaled by 1024
// (keeps values out of fp16 subnormals); zero hist/done. Warp per code.
// ---------------------------------------------------------------------------
__global__ void vq_prep_kernel(const float* __restrict__ emb) {
    const int gtid = blockIdx.x * 256 + threadIdx.x;   // 32768 threads
    const int code = gtid >> 5, lane = gtid & 31;
    float4 v = ((const float4*)emb)[code * 32 + lane];
    double s;
    { double a = v.x, b = v.y, c = v.z, d = v.w; s = a*a + b*b + c*c + d*d; }
    float arr[4] = {v.x, v.y, v.z, v.w};
#pragma unroll
    for (int i = 0; i < 4; i++)
        g_ehalfT[(size_t)(lane * 4 + i) * NUM_EMB + code] =
            __float2half_rn(arr[i] * 1024.0f);
    s = wsumd(s);
    if (lane == 0) { g_be[code] = (float)s; g_hist[code] = 0; }
    if (gtid == 0) g_done = 0;
}

// ---------------------------------------------------------------------------
// main: fp16 HFMA2 screening GEMM, 128 threads with an 8x8 (tokenpair x code)
// register tile (256-reg budget: no spills), double-buffered B staging,
// half-warp shfl fold, exact fp32 rescore (R3 bit-exact chain) + outputs.
// ---------------------------------------------------------------------------
__global__ __launch_bounds__(NTHR, 2)
void vq_main_kernel(const float* __restrict__ x,
                    const float* __restrict__ emb,
                    float* __restrict__ out)
{
    extern __shared__ __align__(16) char dsm[];
    float*     sxf   = (float*)(dsm + SM_SXF);
    int*       scnt  = (int*)(dsm + SM_CNT);
    uint16_t*  slist = (uint16_t*)(dsm + SM_LIST);

    const int tid = threadIdx.x;          // 128
    const int tx  = tid & 15;             // codes tx + 16j (strided, cf-free)
    const int ty  = tid >> 4;             // 0..7: token pairs ty*8 .. ty*8+7
    const int m0  = blockIdx.x * BM;

    // ---- zero this block's one-hot rows (big DRAM op, overlaps GEMM) ----
    {
        float2* enc2 = (float2*)(out + OUT_ENC);
        size_t base = (size_t)m0 * (NUM_EMB / 2);
        for (int i = tid; i < BM * NUM_EMB / 2; i += NTHR)
            enc2[base + i] = make_float2(0.f, 0.f);
    }

    // ---- A tile: x -> fp16 [k][tokenpair]; fused exact sx (double) ----
    {
        const int t = tid;                // one token per thread
        const float4* xr = (const float4*)(x + (size_t)(m0 + t) * EMB_DIM);
        const int pair = t >> 1, ln = t & 1;
        double sp = 0.0;
#pragma unroll 8
        for (int c = 0; c < 32; c++) {
            float4 v = xr[c];
            const int k = c * 4;
            float arr[4] = {v.x, v.y, v.z, v.w};
#pragma unroll
            for (int i = 0; i < 4; i++)
                *(__half*)(dsm + SM_A + (size_t)((k + i) * APAD + pair) * 4
                           + ln * 2) = __float2half_rn(arr[i]);
            double a = v.x, b = v.y, cc = v.z, d = v.w;
            sp += a * a; sp += b * b; sp += cc * cc; sp += d * d;
        }
        sxf[t] = (float)sp;
        scnt[t] = 0;
    }
    __syncthreads();

    // per-token running min / margin in registers (16 tokens per thread)
    float rmin[8][2], delta[8][2];
#pragma unroll
    for (int p = 0; p < 8; p++)
#pragma unroll
        for (int q = 0; q < 2; q++) {
            rmin[p][q]  = INFINITY;
            const float sx = sxf[ty * 16 + 2 * p + q];
            delta[p][q] = 2e-3f * fmaxf(1.0f, sqrtf(sx * 0.0078125f));
        }

    // ---- screening: 32 stages (ct = s>>2, ks = s&3), double-buffered B ----
    const int lr_c2 = tid & 63;           // staging: code pair (0..63)
    const int lr_k0 = tid >> 6;           // staging: k parity (0..1)
    unsigned u[16];
    // prologue: prefetch stage 0
    {
        const __half* Esrc = g_ehalfT;    // ks=0, ct=0
#pragma unroll
        for (int r = 0; r < 16; r++)
            u[r] = *(const unsigned*)(Esrc
                + (size_t)(r * 2 + lr_k0) * NUM_EMB + lr_c2 * 2);
    }

    half2 acc[8][8];
    for (int s = 0; s < 32; s++) {
        char* buf = dsm + (s & 1 ? SM_B1 : SM_B0);
        // store prefetched chunk (dup'd half2) into this stage's buffer
#pragma unroll
        for (int r = 0; r < 16; r++) {
            const int k = r * 2 + lr_k0;
            half2 dlo = __half2half2(
                __ushort_as_half((unsigned short)(u[r] & 0xffffu)));
            half2 dhi = __half2half2(
                __ushort_as_half((unsigned short)(u[r] >> 16)));
            uint2 w; w.x = *(unsigned*)&dlo; w.y = *(unsigned*)&dhi;
            *(uint2*)(buf + (size_t)(k * BPAD + lr_c2 * 2) * 4) = w;
        }
        __syncthreads();

        // prefetch next stage (hidden behind compute)
        if (s < 31) {
            const int sn = s + 1;
            const __half* Esrc = g_ehalfT
                + (size_t)((sn & 3) * 32) * NUM_EMB + (sn >> 2) * 128;
#pragma unroll
            for (int r = 0; r < 16; r++)
                u[r] = *(const unsigned*)(Esrc
                    + (size_t)(r * 2 + lr_k0) * NUM_EMB + lr_c2 * 2);
        }

        if ((s & 3) == 0) {
#pragma unroll
            for (int p = 0; p < 8; p++)
#pragma unroll
                for (int j = 0; j < 8; j++)
                    acc[p][j] = __half2half2(
                        __ushort_as_half((unsigned short)0));
        }

        // HFMA2 inner loop over this 32-k chunk: 8x8 tile
#pragma unroll 2
        for (int k = 0; k < 32; k++) {
            const int kg = (s & 3) * 32 + k;
            const char* arow = dsm + SM_A + (size_t)(kg * APAD + ty * 8) * 4;
            uint4 av0 = *(const uint4*)arow;          // pairs 0..3
            uint4 av1 = *(const uint4*)(arow + 16);   // pairs 4..7
            half2 a[8];
            a[0] = *(half2*)&av0.x; a[1] = *(half2*)&av0.y;
            a[2] = *(half2*)&av0.z; a[3] = *(half2*)&av0.w;
            a[4] = *(half2*)&av1.x; a[5] = *(half2*)&av1.y;
            a[6] = *(half2*)&av1.z; a[7] = *(half2*)&av1.w;
            const half2* br = (const half2*)buf + k * BPAD;
#pragma unroll
            for (int j = 0; j < 8; j++) {
                half2 b = br[tx + 16 * j];            // conflict-free LDS.32
#pragma unroll
                for (int p = 0; p < 8; p++)
                    acc[p][j] = __hfma2(a[p], b, acc[p][j]);
            }
        }

        // ---- end of ct: half-warp fold (no block sync) ----
        if ((s & 3) == 3) {
            const int ct = s >> 2;
            float tmin[8][2];
#pragma unroll
            for (int p = 0; p < 8; p++) { tmin[p][0] = INFINITY; tmin[p][1] = INFINITY; }
#pragma unroll
            for (int j = 0; j < 8; j++) {
                const int kk = ct * 128 + tx + 16 * j;
                const float be = __ldg(&g_be[kk]);
#pragma unroll
                for (int p = 0; p < 8; p++) {
                    float2 df = __half22float2(acc[p][j]);
                    // s = be - 2*dot = be - (2/1024)*dot'  (exact pow2 scale)
                    tmin[p][0] = fminf(tmin[p][0],
                                       __fmaf_rn(-0.001953125f, df.x, be));
                    tmin[p][1] = fminf(tmin[p][1],
                                       __fmaf_rn(-0.001953125f, df.y, be));
                }
            }
            // butterfly min across the 16 owner lanes (order-independent)
#pragma unroll
            for (int m = 1; m <= 8; m <<= 1)
#pragma unroll
                for (int p = 0; p < 8; p++) {
                    tmin[p][0] = fminf(tmin[p][0],
                        __shfl_xor_sync(~0u, tmin[p][0], m));
                    tmin[p][1] = fminf(tmin[p][1],
                        __shfl_xor_sync(~0u, tmin[p][1], m));
                }
            float thr[8][2];
#pragma unroll
            for (int p = 0; p < 8; p++)
#pragma unroll
                for (int q = 0; q < 2; q++) {
                    rmin[p][q] = fminf(rmin[p][q], tmin[p][q]);
                    thr[p][q]  = rmin[p][q] + delta[p][q];
                }
#pragma unroll
            for (int j = 0; j < 8; j++) {
                const int kk = ct * 128 + tx + 16 * j;
                const float be = __ldg(&g_be[kk]);
#pragma unroll
                for (int p = 0; p < 8; p++) {
                    float2 df = __half22float2(acc[p][j]);
                    const int t0 = ty * 16 + 2 * p;
                    float s0 = __fmaf_rn(-0.001953125f, df.x, be);
                    float s1 = __fmaf_rn(-0.001953125f, df.y, be);
                    if (s0 <= thr[p][0]) {
                        int i = atomicAdd(scnt + t0, 1);
                        if (i < CAP) slist[t0 * CAP + i] = (uint16_t)kk;
                    }
                    if (s1 <= thr[p][1]) {
                        int i = atomicAdd(scnt + t0 + 1, 1);
                        if (i < CAP) slist[(t0 + 1) * CAP + i] = (uint16_t)kk;
                    }
                }
            }
        }
    }
    __syncthreads();   // lists complete; SM_A free for epilogue reuse

    // ---- phase 2: exact rescore (R3 bit-exact arithmetic) ----
    int*    s_bk = (int*)(dsm + SM2_SBK);
    double* lred = (double*)(dsm + SM2_LRED);
    double* lacc = (double*)(dsm + SM2_LACC);
    {
        const int row = m0 + tid;
        const float sxe = sxf[tid];
        const float* xr = x + (size_t)row * EMB_DIM;
        float bv = INFINITY;
        int   bk = 0;
        const int nc = scnt[tid];
        if (nc <= 0 || nc > CAP) {
            // safety fallback: full exact scan (nc>=1 is structural)
            for (int k = 0; k < NUM_EMB; k++) {
                float dot = exact_dot(xr, emb + (size_t)k * EMB_DIM);
                float d = __fsub_rn(__fadd_rn(sxe, g_be[k]),
                                    __fmul_rn(2.0f, dot));
                if (d < bv || (d == bv && k < bk)) { bv = d; bk = k; }
            }
        } else {
            bk = NUM_EMB - 1;
            // min over candidate set: order-independent -> deterministic
            for (int i = 0; i < nc; i++) {
                const int k = slist[tid * CAP + i];
                float dot = exact_dot(xr, emb + (size_t)k * EMB_DIM);
                float d = __fsub_rn(__fadd_rn(sxe, g_be[k]),
                                    __fmul_rn(2.0f, dot));
                if (d < bv || (d == bv && k < bk)) { bv = d; bk = k; }
            }
        }
        s_bk[tid] = bk;
        out[(size_t)OUT_ENC + (size_t)row * NUM_EMB + bk] = 1.0f;
        atomicAdd(&g_hist[bk], 1);   // integer atomic: deterministic
    }
    __syncthreads();

    // ---- cooperative coalesced quantized_st + loss (32-bit stores) ----
    double lsum = 0.0;
    float* oq = out + OUT_Q + (size_t)m0 * EMB_DIM;
    const float* xq = x + (size_t)m0 * EMB_DIM;
    for (int e = tid; e < BM * EMB_DIM; e += NTHR) {
        const int row = e >> 7;
        const int col = e & 127;
        const float xv = xq[e];
        const float qv = emb[(size_t)s_bk[row] * EMB_DIM + col];
        const float d  = __fsub_rn(qv, xv);
        oq[e] = __fadd_rn(xv, d);        // fl(x + fl(q-x)), exact STE math
        lsum += (double)d * (double)d;
    }
    lred[tid] = lsum;
    __syncthreads();
    for (int s = NTHR / 2; s > 0; s >>= 1) {
        if (tid < s) lred[tid] += lred[tid + s];
        __syncthreads();
    }
    if (tid == 0) g_lpart[blockIdx.x] = lred[0];

    // ---- last block computes the scalars (fused finalize) ----
    __shared__ bool is_last;
    __threadfence();
    if (tid == 0) {
        unsigned v = atomicAdd(&g_done, 1u);
        is_last = (v == NBLK - 1);
    }
    __syncthreads();
    if (!is_last) return;

    double ent = 0.0;
#pragma unroll
    for (int b = 0; b < 8; b++) {
        double pr = (double)g_hist[tid * 8 + b] / (double)N_TOKENS;
        ent += pr * log(pr + 1e-10);
    }
    double ls = 0.0;
#pragma unroll
    for (int b = 0; b < 4; b++) ls += g_lpart[tid * 4 + b];
    lred[tid] = ent;
    lacc[tid] = ls;
    __syncthreads();
    for (int s = NTHR / 2; s > 0; s >>= 1) {
        if (tid < s) { lred[tid] += lred[tid + s]; lacc[tid] += lacc[tid + s]; }
        __syncthreads();
    }
    if (tid == 0) {
        out[OUT_PERP] = (float)exp(-lred[0]);
        out[OUT_LOSS] = (float)(lacc[0] / ((double)N_TOKENS * (double)EMB_DIM));
    }
}

// ---------------------------------------------------------------------------
extern "C" void kernel_launch(void* const* d_in, const int* in_sizes, int n_in,
                              void* d_out, int out_size) {
    const float* x   = (const float*)d_in[0];   // inputs [65536,128]
    const float* emb = (const float*)d_in[1];   // emb_w  [1024,128]
    float* out = (float*)d_out;

    cudaFuncSetAttribute(vq_main_kernel,
                         cudaFuncAttributeMaxDynamicSharedMemorySize, DSMEM);
    vq_prep_kernel<<<NUM_EMB * 32 / 256, 256>>>(emb);
    vq_main_kernel<<<NBLK, NTHR, DSMEM>>>(x, emb, out);
}

// round 17
// speedup vs baseline: 1.1419x; 1.1183x over previous
#include <cuda_runtime.h>
#include <cuda_fp16.h>
#include <math.h>
#include <stdint.h>

#define N_TOKENS 65536
#define EMB_DIM  128
#define NUM_EMB  1024

// Output tuple flattened scalar-wise in reference-return order:
// (e_latent_loss, quantized_st[N,D], perplexity, encodings[N,K])
#define OUT_LOSS 0
#define OUT_Q    1
#define OUT_PERP (1 + N_TOKENS * EMB_DIM)        // 8388609
#define OUT_ENC  (2 + N_TOKENS * EMB_DIM)        // 8388610 (even -> 8B-aligned)

#define BM   128
#define NBLK (N_TOKENS / BM)     // 512
#define NTHR 256
#define CAP  32                  // candidate list capacity per token

#define APAD 68                  // A tile: half2 stride per k-row (272B)
#define BPAD 128                 // B tile: half2 per k-row (512B, no pad: bcast)
#define STAGE_BYTES (32 * BPAD * 4)   // 16384 per stage slab

// dynamic smem layout (bytes)
#define SM_A    0                // 34816 : A fp16 [k][tokenpair] half2
#define SM_B0   34816            // 16384 : B buffer 0
#define SM_B1   51200            // 16384 : B buffer 1
#define SM_SXP  67584            // 2048  : double sx partials[256]
#define SM_SXF  69632            // 512   : float sx[128]
#define SM_CNT  70144            // 512   : int scnt[128]
#define SM_LIST 70656            // 8192  : uint16 slist[128][CAP]
#define DSMEM   78848
// epilogue reuse inside SM_A (after screening):
#define SM2_SBK  0               // 512 : int bk[128]
#define SM2_LRED 512             // 2048: double lred[256]
#define SM2_LACC 2560            // 2048: double lacc[256]

// pre-duplicated fp16 codebook, stage-contiguous: [ct*4+ks][k(32)][code(128)]
__device__ __align__(16) half2 g_edup[32 * 32 * 128];   // 512 KB
__device__ float  g_be[NUM_EMB];     // fl32 of exact ||e_k||^2
__device__ int    g_hist[NUM_EMB];   // code counts
__device__ double g_lpart[NBLK];     // per-block loss partials
__device__ unsigned int g_done;      // last-block-done counter

__device__ __forceinline__ uint32_t smem_u32(const void* p) {
    uint32_t a;
    asm("{ .reg .u64 t; cvta.to.shared.u64 t, %1; cvt.u32.u64 %0, t; }"
        : "=r"(a) : "l"(p));
    return a;
}
__device__ __forceinline__ void cp_async16(uint32_t dst, const void* src) {
    uint64_t g;
    asm("cvta.to.global.u64 %0, %1;" : "=l"(g) : "l"(src));
    asm volatile("cp.async.cg.shared.global [%0], [%1], 16;"
                 :: "r"(dst), "l"(g));
}
#define CP_COMMIT() asm volatile("cp.async.commit_group;" ::: "memory")
#define CP_WAIT0()  asm volatile("cp.async.wait_group 0;" ::: "memory")

__device__ __forceinline__ double wsumd(double v) {
#pragma unroll
    for (int o = 16; o > 0; o >>= 1) v += __shfl_down_sync(~0u, v, o);
    return v;   // valid on lane 0
}

// exact sequential-k fp32 dot (reference accumulation order), float4 loads
__device__ __forceinline__ float exact_dot(const float* __restrict__ xr,
                                           const float* __restrict__ er) {
    const float4* x4 = (const float4*)xr;
    const float4* e4 = (const float4*)er;
    float dot = 0.f;
#pragma unroll 4
    for (int q = 0; q < EMB_DIM / 4; q++) {
        float4 xv = x4[q], ev = e4[q];
        dot = __fmaf_rn(xv.x, ev.x, dot);
        dot = __fmaf_rn(xv.y, ev.y, dot);
        dot = __fmaf_rn(xv.z, ev.z, dot);
        dot = __fmaf_rn(xv.w, ev.w, dot);
    }
    return dot;
}

// ---------------------------------------------------------------------------
// prep: exact double code norms; pre-duplicated fp16 codebook (x1024 scale,
// stage-contiguous layout for cp.async staging); zero hist/done. Warp/code.
// ---------------------------------------------------------------------------
__global__ void vq_prep_kernel(const float* __restrict__ emb) {
    const int gtid = blockIdx.x * 256 + threadIdx.x;   // 32768 threads
    const int code = gtid >> 5, lane = gtid & 31;
    float4 v = ((const float4*)emb)[code * 32 + lane];
    double s;
    { double a = v.x, b = v.y, c = v.z, d = v.w; s = a*a + b*b + c*c + d*d; }
    float arr[4] = {v.x, v.y, v.z, v.w};
    const int ct = code >> 7, c = code & 127;
#pragma unroll
    for (int i = 0; i < 4; i++) {
        const int k = lane * 4 + i;
        const int ks = k >> 5, kk = k & 31;
        __half h = __float2half_rn(arr[i] * 1024.0f);
        g_edup[(size_t)(((ct * 4 + ks) * 32 + kk)) * 128 + c]
            = __half2half2(h);
    }
    s = wsumd(s);
    if (lane == 0) { g_be[code] = (float)s; g_hist[code] = 0; }
    if (gtid == 0) g_done = 0;
}

// ---------------------------------------------------------------------------
// main: fp16 HFMA2 screening GEMM (4x8 tile, 256 thr, occ 2) with cp.async
// double-buffered B staging from the pre-dup'd codebook, fully unrolled k
// loop (immediate LDS offsets), half-warp shfl fold, exact fp32 rescore (R3
// bit-exact chain) + fused outputs.
// ---------------------------------------------------------------------------
__global__ __launch_bounds__(NTHR, 2)
void vq_main_kernel(const float* __restrict__ x,
                    const float* __restrict__ emb,
                    float* __restrict__ out)
{
    extern __shared__ __align__(16) char dsm[];
    double*    sxp   = (double*)(dsm + SM_SXP);
    float*     sxf   = (float*)(dsm + SM_SXF);
    int*       scnt  = (int*)(dsm + SM_CNT);
    uint16_t*  slist = (uint16_t*)(dsm + SM_LIST);

    const int tid = threadIdx.x;          // 256
    const int tx  = tid & 15;             // codes tx + 16j (strided)
    const int ty  = tid >> 4;             // token pairs ty*4 .. ty*4+3
    const int m0  = blockIdx.x * BM;

    const uint32_t uB0 = smem_u32(dsm + SM_B0);
    const uint32_t uB1 = smem_u32(dsm + SM_B1);

    // ---- issue stage-0 B copy immediately (overlaps everything below) ----
#pragma unroll
    for (int i = 0; i < 4; i++) {
        const int idx = i * NTHR + tid;               // 0..1023 chunks of 16B
        cp_async16(uB0 + idx * 16, (const char*)g_edup + idx * 16);
    }
    CP_COMMIT();

    // ---- zero this block's one-hot rows (big DRAM op, overlaps GEMM) ----
    {
        float2* enc2 = (float2*)(out + OUT_ENC);
        size_t base = (size_t)m0 * (NUM_EMB / 2);
        for (int i = tid; i < BM * NUM_EMB / 2; i += NTHR)
            enc2[base + i] = make_float2(0.f, 0.f);
    }

    // ---- A tile: x -> fp16 [k][tokenpair]; fused sx partials (double) ----
    {
        const int t = tid >> 1, kh = tid & 1;
        const float4* xr = (const float4*)(x + (size_t)(m0 + t) * EMB_DIM)
                           + kh * 16;
        const int pair = t >> 1, ln = t & 1;
        double sp = 0.0;
#pragma unroll 4
        for (int c = 0; c < 16; c++) {
            float4 v = xr[c];
            const int k = kh * 64 + c * 4;
            float arr[4] = {v.x, v.y, v.z, v.w};
#pragma unroll
            for (int i = 0; i < 4; i++)
                *(__half*)(dsm + SM_A + (size_t)((k + i) * APAD + pair) * 4
                           + ln * 2) = __float2half_rn(arr[i]);
            double a = v.x, b = v.y, cc = v.z, d = v.w;
            sp += a * a; sp += b * b; sp += cc * cc; sp += d * d;
        }
        sxp[tid] = sp;   // partial for token t, half kh (fixed pairing)
    }
    if (tid < 128) scnt[tid] = 0;
    __syncthreads();
    if (tid < 128) sxf[tid] = (float)(sxp[tid * 2] + sxp[tid * 2 + 1]);
    __syncthreads();

    // per-token running min / margin in registers (tokens ty*8 .. ty*8+7)
    float rmin[4][2], delta[4][2];
#pragma unroll
    for (int p = 0; p < 4; p++)
#pragma unroll
        for (int q = 0; q < 2; q++) {
            rmin[p][q]  = INFINITY;
            const float sx = sxf[ty * 8 + 2 * p + q];
            delta[p][q] = 2e-3f * fmaxf(1.0f, sqrtf(sx * 0.0078125f));
        }

    // ---- screening: 32 stages (ct = s>>2, ks = s&3), cp.async dbl-buffer ---
    half2 acc[4][8];
    for (int s = 0; s < 32; s++) {
        CP_WAIT0();          // stage-s copy landed (this thread's chunks)
        __syncthreads();     // all threads' chunks visible; s-1 reads done

        // issue copy for stage s+1 into the other buffer (overlaps compute)
        if (s < 31) {
            const uint32_t uDst = (s & 1) ? uB0 : uB1;
            const char* src = (const char*)g_edup + (size_t)(s + 1) * STAGE_BYTES;
#pragma unroll
            for (int i = 0; i < 4; i++) {
                const int idx = i * NTHR + tid;
                cp_async16(uDst + idx * 16, src + idx * 16);
            }
            CP_COMMIT();
        }

        if ((s & 3) == 0) {
#pragma unroll
            for (int p = 0; p < 4; p++)
#pragma unroll
                for (int j = 0; j < 8; j++)
                    acc[p][j] = __half2half2(
                        __ushort_as_half((unsigned short)0));
        }

        // fully unrolled HFMA2 inner loop: immediate LDS offsets, no IMADs
        const char* buf   = dsm + ((s & 1) ? SM_B1 : SM_B0);
        const char* aBase = dsm + SM_A
            + (size_t)((s & 3) * 32 * APAD + ty * 4) * 4;
        const half2* bBase = (const half2*)buf + tx;
#pragma unroll
        for (int k = 0; k < 32; k++) {
            uint4 av = *(const uint4*)(aBase + k * (APAD * 4));
            half2 a0 = *(half2*)&av.x, a1 = *(half2*)&av.y;
            half2 a2 = *(half2*)&av.z, a3 = *(half2*)&av.w;
            const half2* br = bBase + k * BPAD;
#pragma unroll
            for (int j = 0; j < 8; j++) {
                half2 b = br[16 * j];             // bcast-dedup'd LDS.32
                acc[0][j] = __hfma2(a0, b, acc[0][j]);
                acc[1][j] = __hfma2(a1, b, acc[1][j]);
                acc[2][j] = __hfma2(a2, b, acc[2][j]);
                acc[3][j] = __hfma2(a3, b, acc[3][j]);
            }
        }

        // ---- end of ct: half-warp fold (no block sync) ----
        if ((s & 3) == 3) {
            const int ct = s >> 2;
            float tmin[4][2];
#pragma unroll
            for (int p = 0; p < 4; p++) { tmin[p][0] = INFINITY; tmin[p][1] = INFINITY; }
#pragma unroll
            for (int j = 0; j < 8; j++) {
                const int kk = ct * 128 + tx + 16 * j;
                const float be = __ldg(&g_be[kk]);
#pragma unroll
                for (int p = 0; p < 4; p++) {
                    float2 df = __half22float2(acc[p][j]);
                    // s = be - 2*dot = be - (2/1024)*dot'  (exact pow2 scale)
                    tmin[p][0] = fminf(tmin[p][0],
                                       __fmaf_rn(-0.001953125f, df.x, be));
                    tmin[p][1] = fminf(tmin[p][1],
                                       __fmaf_rn(-0.001953125f, df.y, be));
                }
            }
            // butterfly min across the 16 owner lanes (order-independent)
#pragma unroll
            for (int m = 1; m <= 8; m <<= 1)
#pragma unroll
                for (int p = 0; p < 4; p++) {
                    tmin[p][0] = fminf(tmin[p][0],
                        __shfl_xor_sync(~0u, tmin[p][0], m));
                    tmin[p][1] = fminf(tmin[p][1],
                        __shfl_xor_sync(~0u, tmin[p][1], m));
                }
            float thr[4][2];
#pragma unroll
            for (int p = 0; p < 4; p++)
#pragma unroll
                for (int q = 0; q < 2; q++) {
                    rmin[p][q] = fminf(rmin[p][q], tmin[p][q]);
                    thr[p][q]  = rmin[p][q] + delta[p][q];
                }
#pragma unroll
            for (int j = 0; j < 8; j++) {
                const int kk = ct * 128 + tx + 16 * j;
                const float be = __ldg(&g_be[kk]);
#pragma unroll
                for (int p = 0; p < 4; p++) {
                    float2 df = __half22float2(acc[p][j]);
                    const int t0 = ty * 8 + 2 * p;
                    float s0 = __fmaf_rn(-0.001953125f, df.x, be);
                    float s1 = __fmaf_rn(-0.001953125f, df.y, be);
                    if (s0 <= thr[p][0]) {
                        int i = atomicAdd(scnt + t0, 1);
                        if (i < CAP) slist[t0 * CAP + i] = (uint16_t)kk;
                    }
                    if (s1 <= thr[p][1]) {
                        int i = atomicAdd(scnt + t0 + 1, 1);
                        if (i < CAP) slist[(t0 + 1) * CAP + i] = (uint16_t)kk;
                    }
                }
            }
        }
    }
    __syncthreads();   // lists complete; SM_A free for epilogue reuse

    // ---- phase 2: exact rescore (R3 bit-exact arithmetic) ----
    int*    s_bk = (int*)(dsm + SM2_SBK);
    double* lred = (double*)(dsm + SM2_LRED);
    double* lacc = (double*)(dsm + SM2_LACC);
    if (tid < 128) {
        const int row = m0 + tid;
        const float sxe = sxf[tid];
        const float* xr = x + (size_t)row * EMB_DIM;
        float bv = INFINITY;
        int   bk = 0;
        const int nc = scnt[tid];
        if (nc <= 0 || nc > CAP) {
            // safety fallback: full exact scan (nc>=1 is structural)
            for (int k = 0; k < NUM_EMB; k++) {
                float dot = exact_dot(xr, emb + (size_t)k * EMB_DIM);
                float d = __fsub_rn(__fadd_rn(sxe, g_be[k]),
                                    __fmul_rn(2.0f, dot));
                if (d < bv || (d == bv && k < bk)) { bv = d; bk = k; }
            }
        } else {
            bk = NUM_EMB - 1;
            // min over candidate set: order-independent -> deterministic
            for (int i = 0; i < nc; i++) {
                const int k = slist[tid * CAP + i];
                float dot = exact_dot(xr, emb + (size_t)k * EMB_DIM);
                float d = __fsub_rn(__fadd_rn(sxe, g_be[k]),
                                    __fmul_rn(2.0f, dot));
                if (d < bv || (d == bv && k < bk)) { bv = d; bk = k; }
            }
        }
        s_bk[tid] = bk;
        out[(size_t)OUT_ENC + (size_t)row * NUM_EMB + bk] = 1.0f;
        atomicAdd(&g_hist[bk], 1);   // integer atomic: deterministic
    }
    __syncthreads();

    // ---- cooperative coalesced quantized_st + loss (32-bit stores) ----
    double lsum = 0.0;
    float* oq = out + OUT_Q + (size_t)m0 * EMB_DIM;
    const float* xq = x + (size_t)m0 * EMB_DIM;
    for (int e = tid; e < BM * EMB_DIM; e += NTHR) {
        const int row = e >> 7;
        const int col = e & 127;
        const float xv = xq[e];
        const float qv = emb[(size_t)s_bk[row] * EMB_DIM + col];
        const float d  = __fsub_rn(qv, xv);
        oq[e] = __fadd_rn(xv, d);        // fl(x + fl(q-x)), exact STE math
        lsum += (double)d * (double)d;
    }
    lred[tid] = lsum;
    __syncthreads();
    for (int s = NTHR / 2; s > 0; s >>= 1) {
        if (tid < s) lred[tid] += lred[tid + s];
        __syncthreads();
    }
    if (tid == 0) g_lpart[blockIdx.x] = lred[0];

    // ---- last block computes the scalars (fused finalize) ----
    __shared__ bool is_last;
    __threadfence();
    if (tid == 0) {
        unsigned v = atomicAdd(&g_done, 1u);
        is_last = (v == NBLK - 1);
    }
    __syncthreads();
    if (!is_last) return;

    double ent = 0.0;
#pragma unroll
    for (int b = 0; b < 4; b++) {
        double pr = (double)g_hist[tid * 4 + b] / (double)N_TOKENS;
        ent += pr * log(pr + 1e-10);
    }
    double ls = 0.0;
#pragma unroll
    for (int b = 0; b < 2; b++) ls += g_lpart[tid * 2 + b];
    lred[tid] = ent;
    lacc[tid] = ls;
    __syncthreads();
    for (int s = NTHR / 2; s > 0; s >>= 1) {
        if (tid < s) { lred[tid] += lred[tid + s]; lacc[tid] += lacc[tid + s]; }
        __syncthreads();
    }
    if (tid == 0) {
        out[OUT_PERP] = (float)exp(-lred[0]);
        out[OUT_LOSS] = (float)(lacc[0] / ((double)N_TOKENS * (double)EMB_DIM));
    }
}

// ---------------------------------------------------------------------------
extern "C" void kernel_launch(void* const* d_in, const int* in_sizes, int n_in,
                              void* d_out, int out_size) {
    const float* x   = (const float*)d_in[0];   // inputs [65536,128]
    const float* emb = (const float*)d_in[1];   // emb_w  [1024,128]
    float* out = (float*)d_out;

    cudaFuncSetAttribute(vq_main_kernel,
                         cudaFuncAttributeMaxDynamicSharedMemorySize, DSMEM);
    vq_prep_kernel<<<NUM_EMB * 32 / 256, 256>>>(emb);
    vq_main_kernel<<<NBLK, NTHR, DSMEM>>>(x, emb, out);
}